// round 13
// baseline (speedup 1.0000x reference)
#include <cuda_runtime.h>

#define NN  400
#define FF  240
#define CC  32
#define LL  1440

// ---------------- scratch (device globals; no allocation allowed) ----------------
__device__ __align__(16) float g_U[NN*CC];
__device__ __align__(16) float g_V[NN*CC];
__device__ __align__(16) float g_aggi[NN*CC];
__device__ __align__(16) float g_aggj[NN*CC];
__device__ __align__(16) float g_e2 [NN*NN];
__device__ __align__(16) float g_e2T[NN*NN];
__device__ __align__(16) float g_aT [NN*NN];
__device__ __align__(16) float g_eT [NN*NN];
__device__ __align__(16) float g_x2[NN*FF];
__device__ __align__(16) float g_x3[NN*FF];
__device__ __align__(16) float g_W2[304*64];   // nw1 @ [sw2U | sw2V]
__device__ __align__(16) float g_b2[64];       // nb1 @ [sw2U | sw2V]

// ---------------- uv v3 body: [U|V](2 rows) with 8-way K-split ----------------
__device__ __forceinline__ void uv3_body(
    const float* __restrict__ x, const float* __restrict__ sw,
    float* __restrict__ U, float* __restrict__ V,
    int r0, int tid, float* xs /*2*FF*/, float* red /*7*2*64*/)
{
    for (int idx = tid; idx < 2 * FF / 4; idx += 512)
        ((float4*)xs)[idx] = ((const float4*)(x + r0 * FF))[idx];
    __syncthreads();

    int kq   = tid >> 6;          // 0..7
    int slot = tid & 63;
    int half = slot >> 5;         // 0 -> U, 1 -> V
    int c    = slot & 31;
    int kbeg = kq * 30;

    const float* wp = sw + (half * FF + kbeg) * CC + c;
    float w0 = __ldg(wp);
    float w1 = __ldg(wp + CC);
    float a0 = 0.f, a1 = 0.f;
    const float* x0 = xs + kbeg;
    const float* x1 = xs + FF + kbeg;
#pragma unroll
    for (int k = 0; k < 30; k += 2) {
        float n0 = w0, n1 = w1;
        if (k + 2 < 30) {
            n0 = __ldg(wp + 2 * CC);
            n1 = __ldg(wp + 3 * CC);
        }
        a0 = fmaf(x0[k],     w0, a0);
        a1 = fmaf(x1[k],     w0, a1);
        a0 = fmaf(x0[k + 1], w1, a0);
        a1 = fmaf(x1[k + 1], w1, a1);
        w0 = n0; w1 = n1;
        wp += 2 * CC;
    }
    if (kq > 0) {
        red[(kq - 1) * 128 + slot]      = a0;
        red[(kq - 1) * 128 + 64 + slot] = a1;
    }
    __syncthreads();
    if (kq == 0) {
        float s0 = a0, s1 = a1;
#pragma unroll
        for (int q = 0; q < 7; q++) {
            s0 += red[q * 128 + slot];
            s1 += red[q * 128 + 64 + slot];
        }
        float* dst = half ? V : U;
        dst[r0 * CC + c]       = s0;
        dst[(r0 + 1) * CC + c] = s1;
    }
}

// ---------------- fused prologue ----------------
// y=0: a->aT   y=1: e->eT   y=2: uv3(layer1)   y=3: W2/b2 compose
__global__ __launch_bounds__(512) void pre_kernel(
    const float* __restrict__ a, float* __restrict__ aT,
    const float* __restrict__ e, float* __restrict__ eT,
    const float* __restrict__ x, const float* __restrict__ sw,
    float* __restrict__ U, float* __restrict__ V,
    const float* __restrict__ nw1, const float* __restrict__ nb1,
    const float* __restrict__ sw2,
    float* __restrict__ W2, float* __restrict__ b2)
{
    __shared__ float smem[2 * FF + 7 * 2 * 64 + 64];
    if (blockIdx.y < 2) {
        if (blockIdx.x >= 169) return;
        const float* src = blockIdx.y ? e : a;
        float*       dst = blockIdx.y ? eT : aT;
        float (*tile)[33] = (float(*)[33])smem;
        int tx = threadIdx.x & 31, ty = threadIdx.x >> 5;   // ty 0..15
        int bx = blockIdx.x % 13, by = blockIdx.x / 13;
        int xc = bx * 32 + tx;
#pragma unroll
        for (int dy = 0; dy < 32; dy += 16) {
            int yr = by * 32 + ty + dy;
            if (xc < NN && yr < NN)
                tile[ty + dy][tx] = src[yr * NN + xc];
        }
        __syncthreads();
        int xc2 = by * 32 + tx;
#pragma unroll
        for (int dy = 0; dy < 32; dy += 16) {
            int yr2 = bx * 32 + ty + dy;
            if (xc2 < NN && yr2 < NN)
                dst[yr2 * NN + xc2] = tile[tx][ty + dy];
        }
    } else if (blockIdx.y == 2) {
        uv3_body(x, sw, U, V, blockIdx.x * 2, threadIdx.x,
                 smem, smem + 2 * FF);
    } else {
        // ---- W2/b2 compose: W2[k,c] = sum_f nw1[k,f]*sw2col[f,c]; b2 likewise ----
        const int KTOT = FF + 2 * CC;            // 304
        int idx = blockIdx.x * 512 + threadIdx.x;
        if (idx < KTOT * 64) {
            int k = idx >> 6;
            int c = idx & 63;
            const float* wr = nw1 + k * FF;
            const float* sc = (c < CC) ? (sw2 + c) : (sw2 + FF * CC + (c - CC));
            float acc = 0.f;
#pragma unroll 4
            for (int f = 0; f < FF; f++)
                acc = fmaf(__ldg(&wr[f]), __ldg(&sc[f * CC]), acc);
            W2[k * 64 + c] = acc;
        } else if (idx < KTOT * 64 + 64) {
            int c = idx - KTOT * 64;
            const float* sc = (c < CC) ? (sw2 + c) : (sw2 + FF * CC + (c - CC));
            float acc = 0.f;
#pragma unroll 4
            for (int f = 0; f < FF; f++)
                acc = fmaf(__ldg(&nb1[f]), __ldg(&sc[f * CC]), acc);
            b2[c] = acc;
        }
    }
}

// ---------------- pair v4: 2 rows/block, smem accumulators; grid (200, 2) ----------
__global__ __launch_bounds__(128) void pair_both_kernel(
    const float*  __restrict__ U,
    const float*  __restrict__ V,
    const float*  __restrict__ e,
    const float*  __restrict__ eT,
    const float*  __restrict__ a,
    const float*  __restrict__ aT,
    const float*  __restrict__ we,
    const float*  __restrict__ wet,
    const float*  __restrict__ sb,
    const float*  __restrict__ aiw, const float* __restrict__ aib,
    const float*  __restrict__ ajw, const float* __restrict__ ajb,
    const float*  __restrict__ ew,  const float* __restrict__ eb,
    float* __restrict__ aggi, float* __restrict__ aggj,
    float* __restrict__ e_out, float* __restrict__ e_outT)
{
    __shared__ float4 cw4[2][CC];
    __shared__ float  cew[CC];
    __shared__ float  red[128 * 67];       // [c]=row0, [33+c]=row1; stride 67 odd
    __shared__ float  part0[128], part1[128];

    int b0   = blockIdx.x * 2;
    int side = blockIdx.y;
    int tid  = threadIdx.x;

    const float*  own  = side ? V : U;
    const float4* oth4 = (const float4*)(side ? U : V);
    const float*  eF   = side ? eT : e;
    const float*  eR   = side ? e  : eT;
    const float*  am   = side ? aT : a;
    const float*  gw = side ? ajw : aiw;
    const float*  gb = side ? ajb : aib;
    float* agg_out = side ? aggj : aggi;
    const bool write_e = (side == 0) && (e_out != nullptr);

    if (tid < 2 * CC) {
        int p = tid >> 5, c = tid & 31;
        cw4[p][c] = make_float4(own[(b0 + p) * CC + c] + sb[c], we[c], wet[c], gw[c]);
    }
    if (tid < CC) cew[tid] = write_e ? ew[tid] : 0.f;
    float* my = red + tid * 67;
#pragma unroll
    for (int u = 0; u < 67; u++) my[u] = 0.f;
    __syncthreads();

    float gbias = gb[0];
    float ebias = write_e ? eb[0] : 0.f;

    for (int t = tid; t < NN; t += 128) {
        float v[CC];
#pragma unroll
        for (int c4 = 0; c4 < CC / 4; c4++) {
            float4 vv = __ldg(&oth4[t * (CC / 4) + c4]);
            v[c4 * 4 + 0] = vv.x; v[c4 * 4 + 1] = vv.y;
            v[c4 * 4 + 2] = vv.z; v[c4 * 4 + 3] = vv.w;
        }
        float ef0 = __ldg(&eF[b0 * NN + t]);
        float er0 = __ldg(&eR[b0 * NN + t]);
        float am0 = __ldg(&am[b0 * NN + t]);
        float ef1 = __ldg(&eF[(b0 + 1) * NN + t]);
        float er1 = __ldg(&eR[(b0 + 1) * NN + t]);
        float am1 = __ldg(&am[(b0 + 1) * NN + t]);

        {
            float ai = 0.f, eo = 0.f;
            float s[CC];
#pragma unroll
            for (int c = 0; c < CC; c++) {
                float4 w = cw4[0][c];
                float pre = w.x + v[c];
                pre = fmaf(ef0, w.y, pre);
                pre = fmaf(er0, w.z, pre);
                float sv = fmaxf(pre, 0.f) * am0;
                s[c] = sv;
                ai = fmaf(sv, w.w, ai);
                eo = fmaf(sv, cew[c], eo);
            }
            float att = 1.f / (1.f + __expf(-(ai + gbias)));
            if (write_e) {
                float ev = eo + ebias;
                e_out[b0 * NN + t] = ev;
                e_outT[t * NN + b0] = ev;
            }
#pragma unroll
            for (int c = 0; c < CC; c++)
                my[c] = fmaf(att, s[c], my[c]);
        }
        {
            float ai = 0.f, eo = 0.f;
            float s[CC];
#pragma unroll
            for (int c = 0; c < CC; c++) {
                float4 w = cw4[1][c];
                float pre = w.x + v[c];
                pre = fmaf(ef1, w.y, pre);
                pre = fmaf(er1, w.z, pre);
                float sv = fmaxf(pre, 0.f) * am1;
                s[c] = sv;
                ai = fmaf(sv, w.w, ai);
                eo = fmaf(sv, cew[c], eo);
            }
            float att = 1.f / (1.f + __expf(-(ai + gbias)));
            if (write_e) {
                float ev = eo + ebias;
                e_out[(b0 + 1) * NN + t] = ev;
                e_outT[t * NN + b0 + 1] = ev;
            }
#pragma unroll
            for (int c = 0; c < CC; c++)
                my[33 + c] = fmaf(att, s[c], my[33 + c]);
        }
    }
    __syncthreads();

    {
        int c = tid & 31, g = tid >> 5;
        float s0 = 0.f, s1 = 0.f;
#pragma unroll
        for (int u = 0; u < 32; u++) {
            int base = (g * 32 + u) * 67;
            s0 += red[base + c];
            s1 += red[base + 33 + c];
        }
        part0[tid] = s0;
        part1[tid] = s1;
    }
    __syncthreads();
    if (tid < CC) {
        agg_out[b0 * CC + tid] =
            (part0[tid] + part0[32 + tid]) + (part0[64 + tid] + part0[96 + tid]);
        agg_out[(b0 + 1) * CC + tid] =
            (part1[tid] + part1[32 + tid]) + (part1[64 + tid] + part1[96 + tid]);
    }
}

// ---------------- node v8: float2 col-pairs, 16-way K-split ----------------
// grid (100, 4 [+1 if uv2]): y<4 -> x2 cols (60 each); y==4 -> U2/V2 (64 cols via W2)
__global__ __launch_bounds__(512) void node_gemm_kernel(
    const float* __restrict__ x,
    const float* __restrict__ aggi,
    const float* __restrict__ aggj,
    const float* __restrict__ nw,
    const float* __restrict__ nb,
    float* __restrict__ out,
    const float* __restrict__ W2, const float* __restrict__ b2,
    float* __restrict__ U, float* __restrict__ V)
{
    const int K = FF + 2 * CC;                  // 304 = 16 * 19
    __shared__ __align__(16) float cs[304 * 4]; // transposed: cs[k*4 + r]
    __shared__ float red[15 * 256];             // kq=1..15 partials: 4 rows x <=64 cols

    int r0 = blockIdx.x * 4;
    for (int idx = threadIdx.x; idx < K * 4; idx += 512) {
        int k = idx >> 2, r = idx & 3;
        int row = r0 + r;
        float v;
        if (k < FF)            v = x[row * FF + k];
        else if (k < FF + CC)  v = aggi[row * CC + (k - FF)];
        else                   v = aggj[row * CC + (k - FF - CC)];
        cs[idx] = v;
    }
    __syncthreads();

    bool uv2 = (blockIdx.y == 4);
    int kq   = threadIdx.x >> 5;          // 0..15
    int slot = threadIdx.x & 31;
    int kbeg = kq * 19;
    const float4* cs4 = (const float4*)cs;

    int ncols, wstride, col;
    const float* wbase;
    if (uv2) { ncols = 64; wstride = 64; col = 2 * slot; wbase = W2; }
    else     { ncols = 60; wstride = FF; col = 2 * ((slot < 30) ? slot : 29); wbase = nw + blockIdx.y * 60; }
    bool active = uv2 || (slot < 30);

    float a0 = 0.f, a1 = 0.f, a2 = 0.f, a3 = 0.f;
    float b0 = 0.f, b1 = 0.f, b2r = 0.f, b3 = 0.f;

    const float* wp = wbase + kbeg * wstride + col;
    float2 w = *(const float2*)wp;
#pragma unroll
    for (int kk = 0; kk < 19; kk++) {
        float2 nx = w;
        if (kk + 1 < 19) nx = *(const float2*)(wp + wstride);
        float4 v = cs4[kbeg + kk];
        a0 = fmaf(v.x, w.x, a0); b0  = fmaf(v.x, w.y, b0);
        a1 = fmaf(v.y, w.x, a1); b1  = fmaf(v.y, w.y, b1);
        a2 = fmaf(v.z, w.x, a2); b2r = fmaf(v.z, w.y, b2r);
        a3 = fmaf(v.w, w.x, a3); b3  = fmaf(v.w, w.y, b3);
        w = nx;
        wp += wstride;
    }

    if (active && kq > 0) {
        float* myp = red + (kq - 1) * 256 + 2 * slot;
        myp[0]   = a0; myp[1]   = b0;
        myp[64]  = a1; myp[65]  = b1;
        myp[128] = a2; myp[129] = b2r;
        myp[192] = a3; myp[193] = b3;
    }
    __syncthreads();
    if (active && kq == 0) {
        float sa[4] = {a0, a1, a2, a3};
        float sb2[4] = {b0, b1, b2r, b3};
        const float* p = red + 2 * slot;
#pragma unroll
        for (int q = 0; q < 15; q++) {
#pragma unroll
            for (int r = 0; r < 4; r++) {
                sa[r]  += p[q * 256 + r * 64];
                sb2[r] += p[q * 256 + r * 64 + 1];
            }
        }
        if (uv2) {
            float bias0 = b2[col], bias1 = b2[col + 1];
            float* dst = (col < CC) ? U : V;
            int cc = (col < CC) ? col : col - CC;
#pragma unroll
            for (int r = 0; r < 4; r++)
                *(float2*)&dst[(r0 + r) * CC + cc] =
                    make_float2(sa[r] + bias0, sb2[r] + bias1);
        } else {
            int ocol = blockIdx.y * 60 + col;
            float bias0 = nb[ocol], bias1 = nb[ocol + 1];
#pragma unroll
            for (int r = 0; r < 4; r++)
                *(float2*)&out[(r0 + r) * FF + ocol] =
                    make_float2(sa[r] + bias0, sb2[r] + bias1);
        }
    }
}

// ---------------- final dense v4: 5-way K-split, window-4 prefetch ----------------
__global__ __launch_bounds__(480) void dense_kernel(
    const float* __restrict__ x,
    const float* __restrict__ dw,
    const float* __restrict__ db,
    float* __restrict__ out)
{
    const int KQ = 48;
    __shared__ __align__(16) float xs[FF * 16];
    __shared__ float red[4 * 16 * 96];

    int r0 = blockIdx.x * 16;
    int c0 = blockIdx.y * 96;
    for (int idx = threadIdx.x; idx < FF * 16; idx += 480) {
        int k = idx >> 4, r = idx & 15;
        xs[idx] = x[(r0 + r) * FF + k];
    }
    __syncthreads();

    int kq = threadIdx.x / 96;
    int c  = threadIdx.x % 96;
    int col = c0 + c;
    int kbeg = kq * KQ;

    float acc[16];
#pragma unroll
    for (int r = 0; r < 16; r++) acc[r] = 0.f;

    const float4* xs4 = (const float4*)xs;
    const float* wp = dw + kbeg * LL + col;
    float w0 = __ldg(wp);
    float w1 = __ldg(wp + LL);
    float w2 = __ldg(wp + 2 * LL);
    float w3 = __ldg(wp + 3 * LL);
    for (int k2 = kbeg; k2 < kbeg + KQ; k2 += 4) {
        float n0 = w0, n1 = w1, n2 = w2, n3 = w3;
        if (k2 + 4 < kbeg + KQ) {
            const float* np = wp + 4 * LL;
            n0 = __ldg(np);
            n1 = __ldg(np + LL);
            n2 = __ldg(np + 2 * LL);
            n3 = __ldg(np + 3 * LL);
        }
#pragma unroll
        for (int kk = 0; kk < 4; kk++) {
            float wf = (kk == 0) ? w0 : (kk == 1) ? w1 : (kk == 2) ? w2 : w3;
            float4 a0 = xs4[(k2 + kk) * 4 + 0];
            float4 a1 = xs4[(k2 + kk) * 4 + 1];
            float4 a2 = xs4[(k2 + kk) * 4 + 2];
            float4 a3 = xs4[(k2 + kk) * 4 + 3];
            acc[ 0] = fmaf(a0.x, wf, acc[ 0]);
            acc[ 1] = fmaf(a0.y, wf, acc[ 1]);
            acc[ 2] = fmaf(a0.z, wf, acc[ 2]);
            acc[ 3] = fmaf(a0.w, wf, acc[ 3]);
            acc[ 4] = fmaf(a1.x, wf, acc[ 4]);
            acc[ 5] = fmaf(a1.y, wf, acc[ 5]);
            acc[ 6] = fmaf(a1.z, wf, acc[ 6]);
            acc[ 7] = fmaf(a1.w, wf, acc[ 7]);
            acc[ 8] = fmaf(a2.x, wf, acc[ 8]);
            acc[ 9] = fmaf(a2.y, wf, acc[ 9]);
            acc[10] = fmaf(a2.z, wf, acc[10]);
            acc[11] = fmaf(a2.w, wf, acc[11]);
            acc[12] = fmaf(a3.x, wf, acc[12]);
            acc[13] = fmaf(a3.y, wf, acc[13]);
            acc[14] = fmaf(a3.z, wf, acc[14]);
            acc[15] = fmaf(a3.w, wf, acc[15]);
        }
        w0 = n0; w1 = n1; w2 = n2; w3 = n3;
        wp += 4 * LL;
    }

    if (kq > 0) {
        float* myp = red + (kq - 1) * 1536 + c;
#pragma unroll
        for (int r = 0; r < 16; r++) myp[r * 96] = acc[r];
    }
    __syncthreads();
    if (kq == 0) {
        float bias = db[col];
        const float* p = red + c;
#pragma unroll
        for (int r = 0; r < 16; r++)
            out[(r0 + r) * LL + col] = acc[r] + bias + p[r * 96] + p[1536 + r * 96]
                                       + p[3072 + r * 96] + p[4608 + r * 96];
    }
}

// ---------------- launch ----------------
extern "C" void kernel_launch(void* const* d_in, const int* in_sizes, int n_in,
                              void* d_out, int out_size)
{
    const float* x      = (const float*)d_in[0];
    const float* a      = (const float*)d_in[1];
    const float* e      = (const float*)d_in[2];
    const float* c1_sw  = (const float*)d_in[3];
    const float* c1_sb  = (const float*)d_in[4];
    const float* c1_aiw = (const float*)d_in[5];
    const float* c1_aib = (const float*)d_in[6];
    const float* c1_ajw = (const float*)d_in[7];
    const float* c1_ajb = (const float*)d_in[8];
    const float* c1_nw  = (const float*)d_in[9];
    const float* c1_nb  = (const float*)d_in[10];
    const float* c1_ew  = (const float*)d_in[11];
    const float* c1_eb  = (const float*)d_in[12];
    const float* c2_sw  = (const float*)d_in[13];
    const float* c2_sb  = (const float*)d_in[14];
    const float* c2_aiw = (const float*)d_in[15];
    const float* c2_aib = (const float*)d_in[16];
    const float* c2_ajw = (const float*)d_in[17];
    const float* c2_ajb = (const float*)d_in[18];
    const float* c2_nw  = (const float*)d_in[19];
    const float* c2_nb  = (const float*)d_in[20];
    const float* c2_ew  = (const float*)d_in[21];
    const float* c2_eb  = (const float*)d_in[22];
    const float* dw     = (const float*)d_in[23];
    const float* db     = (const float*)d_in[24];
    float* out = (float*)d_out;

    float *pU, *pV, *pAi, *pAj, *pE2, *pE2T, *pAT, *pET, *pX2, *pX3, *pW2, *pB2;
    cudaGetSymbolAddress((void**)&pU,   g_U);
    cudaGetSymbolAddress((void**)&pV,   g_V);
    cudaGetSymbolAddress((void**)&pAi,  g_aggi);
    cudaGetSymbolAddress((void**)&pAj,  g_aggj);
    cudaGetSymbolAddress((void**)&pE2,  g_e2);
    cudaGetSymbolAddress((void**)&pE2T, g_e2T);
    cudaGetSymbolAddress((void**)&pAT,  g_aT);
    cudaGetSymbolAddress((void**)&pET,  g_eT);
    cudaGetSymbolAddress((void**)&pX2,  g_x2);
    cudaGetSymbolAddress((void**)&pX3,  g_x3);
    cudaGetSymbolAddress((void**)&pW2,  g_W2);
    cudaGetSymbolAddress((void**)&pB2,  g_b2);

    // fused prologue: transposes + layer-1 UV + W2/b2 compose
    pre_kernel<<<dim3(200, 4), 512>>>(a, pAT, e, pET, x, c1_sw, pU, pV,
                                      c1_nw, c1_nb, c2_sw, pW2, pB2);

    // ---- layer 1 ----
    pair_both_kernel<<<dim3(NN / 2, 2), 128>>>(pU, pV, e, pET, a, pAT,
        c1_sw + 480 * CC, c1_sw + 481 * CC, c1_sb,
        c1_aiw, c1_aib, c1_ajw, c1_ajb, c1_ew, c1_eb,
        pAi, pAj, pE2, pE2T);
    // node layer1: also emits U2/V2 directly (y==4 tile)
    node_gemm_kernel<<<dim3(100, 5), 512>>>(x, pAi, pAj, c1_nw, c1_nb, pX2,
                                            pW2, pB2, pU, pV);

    // ---- layer 2 (uv launch eliminated) ----
    pair_both_kernel<<<dim3(NN / 2, 2), 128>>>(pU, pV, pE2, pE2T, a, pAT,
        c2_sw + 480 * CC, c2_sw + 481 * CC, c2_sb,
        c2_aiw, c2_aib, c2_ajw, c2_ajb, nullptr, nullptr,
        pAi, pAj, nullptr, nullptr);
    node_gemm_kernel<<<dim3(100, 4), 512>>>(pX2, pAi, pAj, c2_nw, c2_nb, pX3,
                                            pW2, pB2, nullptr, nullptr);

    // ---- final dense ----
    dense_kernel<<<dim3(25, 15), 480>>>(pX3, dw, db, out);
}

// round 14
// speedup vs baseline: 1.2897x; 1.2897x over previous
#include <cuda_runtime.h>

#define NN  400
#define FF  240
#define CC  32
#define LL  1440

// ---------------- scratch (device globals; no allocation allowed) ----------------
__device__ __align__(16) float g_U[NN*CC];
__device__ __align__(16) float g_V[NN*CC];
__device__ __align__(16) float g_aggi[NN*CC];
__device__ __align__(16) float g_aggj[NN*CC];
__device__ __align__(16) float g_e2 [NN*NN];
__device__ __align__(16) float g_e2T[NN*NN];
__device__ __align__(16) float g_aT [NN*NN];
__device__ __align__(16) float g_eT [NN*NN];
__device__ __align__(16) float g_x2[NN*FF];
__device__ __align__(16) float g_x3[NN*FF];

// ---------------- uv v3 body: [U|V](2 rows) with 8-way K-split ----------------
__device__ __forceinline__ void uv3_body(
    const float* __restrict__ x, const float* __restrict__ sw,
    float* __restrict__ U, float* __restrict__ V,
    int r0, int tid, float* xs /*2*FF*/, float* red /*7*2*64*/)
{
    for (int idx = tid; idx < 2 * FF / 4; idx += 512)
        ((float4*)xs)[idx] = ((const float4*)(x + r0 * FF))[idx];
    __syncthreads();

    int kq   = tid >> 6;          // 0..7
    int slot = tid & 63;
    int half = slot >> 5;         // 0 -> U, 1 -> V
    int c    = slot & 31;
    int kbeg = kq * 30;

    const float* wp = sw + (half * FF + kbeg) * CC + c;
    float w0 = __ldg(wp);
    float w1 = __ldg(wp + CC);
    float a0 = 0.f, a1 = 0.f;
    const float* x0 = xs + kbeg;
    const float* x1 = xs + FF + kbeg;
#pragma unroll
    for (int k = 0; k < 30; k += 2) {
        float n0 = w0, n1 = w1;
        if (k + 2 < 30) {
            n0 = __ldg(wp + 2 * CC);
            n1 = __ldg(wp + 3 * CC);
        }
        a0 = fmaf(x0[k],     w0, a0);
        a1 = fmaf(x1[k],     w0, a1);
        a0 = fmaf(x0[k + 1], w1, a0);
        a1 = fmaf(x1[k + 1], w1, a1);
        w0 = n0; w1 = n1;
        wp += 2 * CC;
    }
    if (kq > 0) {
        red[(kq - 1) * 128 + slot]      = a0;
        red[(kq - 1) * 128 + 64 + slot] = a1;
    }
    __syncthreads();
    if (kq == 0) {
        float s0 = a0, s1 = a1;
#pragma unroll
        for (int q = 0; q < 7; q++) {
            s0 += red[q * 128 + slot];
            s1 += red[q * 128 + 64 + slot];
        }
        float* dst = half ? V : U;
        dst[r0 * CC + c]       = s0;
        dst[(r0 + 1) * CC + c] = s1;
    }
}

// ---------------- fused prologue: y=0 a->aT, y=1 e->eT, y=2 uv3(layer1) -----------
__global__ __launch_bounds__(512) void pre_kernel(
    const float* __restrict__ a, float* __restrict__ aT,
    const float* __restrict__ e, float* __restrict__ eT,
    const float* __restrict__ x, const float* __restrict__ sw,
    float* __restrict__ U, float* __restrict__ V)
{
    __shared__ float smem[2 * FF + 7 * 2 * 64 + 64];
    if (blockIdx.y < 2) {
        if (blockIdx.x >= 169) return;
        const float* src = blockIdx.y ? e : a;
        float*       dst = blockIdx.y ? eT : aT;
        float (*tile)[33] = (float(*)[33])smem;
        int tx = threadIdx.x & 31, ty = threadIdx.x >> 5;   // ty 0..15
        int bx = blockIdx.x % 13, by = blockIdx.x / 13;
        int xc = bx * 32 + tx;
#pragma unroll
        for (int dy = 0; dy < 32; dy += 16) {
            int yr = by * 32 + ty + dy;
            if (xc < NN && yr < NN)
                tile[ty + dy][tx] = src[yr * NN + xc];
        }
        __syncthreads();
        int xc2 = by * 32 + tx;
#pragma unroll
        for (int dy = 0; dy < 32; dy += 16) {
            int yr2 = bx * 32 + ty + dy;
            if (xc2 < NN && yr2 < NN)
                dst[yr2 * NN + xc2] = tile[tx][ty + dy];
        }
    } else {
        uv3_body(x, sw, U, V, blockIdx.x * 2, threadIdx.x,
                 smem, smem + 2 * FF);
    }
}

// ---------------- standalone uv3 (layer 2) ----------------
__global__ __launch_bounds__(512) void uv3_kernel(
    const float* __restrict__ x, const float* __restrict__ sw,
    float* __restrict__ U, float* __restrict__ V)
{
    __shared__ float smem[2 * FF + 7 * 2 * 64];
    uv3_body(x, sw, U, V, blockIdx.x * 2, threadIdx.x, smem, smem + 2 * FF);
}

// ---------------- pair v5: channel-split, register accumulators; grid (400, 2) -----
// Block = 128 thr: warp (4) x t-slot (8) x channel-group (4, lane bits 0-1).
// Each thread: 8 channels of one t; full 32-ch gate dot via 2 butterfly shuffles.
__global__ __launch_bounds__(128) void pair_both_kernel(
    const float*  __restrict__ U,
    const float*  __restrict__ V,
    const float*  __restrict__ e,
    const float*  __restrict__ eT,
    const float*  __restrict__ a,
    const float*  __restrict__ aT,
    const float*  __restrict__ we,
    const float*  __restrict__ wet,
    const float*  __restrict__ sb,
    const float*  __restrict__ aiw, const float* __restrict__ aib,
    const float*  __restrict__ ajw, const float* __restrict__ ajb,
    const float*  __restrict__ ew,  const float* __restrict__ eb,
    float* __restrict__ aggi, float* __restrict__ aggj,
    float* __restrict__ e_out, float* __restrict__ e_outT)
{
    __shared__ float4 cw4s[CC];           // {own[c]+sb[c], we[c], wet[c], gw[c]}
    __shared__ float  cews[CC];
    __shared__ float  red[128 * 9];       // per-thread agg[8], stride 9

    int b    = blockIdx.x;
    int side = blockIdx.y;
    int tid  = threadIdx.x;

    const float*  own  = side ? V : U;
    const float4* oth4 = (const float4*)(side ? U : V);
    const float*  eFrow = (side ? eT : e)  + b * NN;
    const float*  eRrow = (side ? e  : eT) + b * NN;
    const float*  arow  = (side ? aT : a)  + b * NN;
    const float*  gw = side ? ajw : aiw;
    const float*  gb = side ? ajb : aib;
    float* agg_out = side ? aggj : aggi;
    const bool write_e = (side == 0) && (e_out != nullptr);

    if (tid < CC) {
        int c = tid;
        cw4s[c] = make_float4(own[b * CC + c] + sb[c], we[c], wet[c], gw[c]);
        cews[c] = write_e ? ew[c] : 0.f;
    }
    __syncthreads();

    int lane  = tid & 31;
    int warp  = tid >> 5;
    int cg    = lane & 3;          // channel group: channels cg*8..cg*8+7
    int tslot = lane >> 2;         // 0..7
    int t0    = warp * 8 + tslot;  // 0..31

    // channel constants into registers
    float4 cw[8];
    float  ce[8];
#pragma unroll
    for (int u = 0; u < 8; u++) {
        cw[u] = cw4s[cg * 8 + u];
        ce[u] = cews[cg * 8 + u];
    }
    float gbias = gb[0];
    float ebias = write_e ? eb[0] : 0.f;

    float agg[8];
#pragma unroll
    for (int u = 0; u < 8; u++) agg[u] = 0.f;

    for (int t = t0; t < NN; t += 32) {
        float4 o0 = __ldg(&oth4[t * 8 + cg * 2]);
        float4 o1 = __ldg(&oth4[t * 8 + cg * 2 + 1]);
        float ef = __ldg(&eFrow[t]);
        float er = __ldg(&eRrow[t]);
        float am = __ldg(&arow[t]);

        float ov[8] = {o0.x, o0.y, o0.z, o0.w, o1.x, o1.y, o1.z, o1.w};
        float s[8];
        float ai = 0.f, eo = 0.f;
#pragma unroll
        for (int u = 0; u < 8; u++) {
            float pre = cw[u].x + ov[u];
            pre = fmaf(ef, cw[u].y, pre);
            pre = fmaf(er, cw[u].z, pre);
            float sv = fmaxf(pre, 0.f) * am;
            s[u] = sv;
            ai = fmaf(sv, cw[u].w, ai);
            eo = fmaf(sv, ce[u], eo);
        }
        // reduce over the 4 channel-groups (lane bits 0-1)
        ai += __shfl_xor_sync(0xffffffffu, ai, 1);
        ai += __shfl_xor_sync(0xffffffffu, ai, 2);
        float att = 1.f / (1.f + __expf(-(ai + gbias)));
        if (write_e) {
            eo += __shfl_xor_sync(0xffffffffu, eo, 1);
            eo += __shfl_xor_sync(0xffffffffu, eo, 2);
            if (cg == 0) {
                float ev = eo + ebias;
                e_out[b * NN + t] = ev;
                e_outT[t * NN + b] = ev;
            }
        }
#pragma unroll
        for (int u = 0; u < 8; u++)
            agg[u] = fmaf(att, s[u], agg[u]);
    }

    // block reduction: each (c) summed over its 32 owner threads
#pragma unroll
    for (int u = 0; u < 8; u++) red[tid * 9 + u] = agg[u];
    __syncthreads();
    if (tid < CC) {
        int c   = tid;
        int cgc = c >> 3;
        int ch  = c & 7;
        float sum = 0.f;
#pragma unroll
        for (int w = 0; w < 4; w++) {
#pragma unroll
            for (int ts = 0; ts < 8; ts++)
                sum += red[(w * 32 + ts * 4 + cgc) * 9 + ch];
        }
        agg_out[b * CC + c] = sum;
    }
}

// ---------------- node v7: float2 col-pairs, 16-way K-split ----------------
// grid (100 row-tiles of 4, 4 col-tiles of 60); 512 thr = 16 kq x 32 slots (30 active)
__global__ __launch_bounds__(512) void node_gemm_kernel(
    const float* __restrict__ x,
    const float* __restrict__ aggi,
    const float* __restrict__ aggj,
    const float* __restrict__ nw,
    const float* __restrict__ nb,
    float* __restrict__ out)
{
    const int K = FF + 2 * CC;                  // 304 = 16 * 19
    __shared__ __align__(16) float cs[304 * 4]; // transposed: cs[k*4 + r]
    __shared__ float red[15 * 240];             // kq=1..15 partials

    int r0 = blockIdx.x * 4;
    int c0 = blockIdx.y * 60;
    for (int idx = threadIdx.x; idx < K * 4; idx += 512) {
        int k = idx >> 2, r = idx & 3;
        int row = r0 + r;
        float v;
        if (k < FF)            v = x[row * FF + k];
        else if (k < FF + CC)  v = aggi[row * CC + (k - FF)];
        else                   v = aggj[row * CC + (k - FF - CC)];
        cs[idx] = v;
    }
    __syncthreads();

    int kq   = threadIdx.x >> 5;          // 0..15
    int slot = threadIdx.x & 31;
    bool active = (slot < 30);
    int col = c0 + 2 * (active ? slot : 29);
    int kbeg = kq * 19;

    float a0 = 0.f, a1 = 0.f, a2 = 0.f, a3 = 0.f;   // col
    float b0 = 0.f, b1 = 0.f, b2 = 0.f, b3 = 0.f;   // col+1
    const float4* cs4 = (const float4*)cs;

    const float* wp = nw + kbeg * FF + col;
    float2 w = *(const float2*)wp;
#pragma unroll
    for (int kk = 0; kk < 19; kk++) {
        float2 nx = w;
        if (kk + 1 < 19) nx = *(const float2*)(wp + FF);
        float4 v = cs4[kbeg + kk];
        a0 = fmaf(v.x, w.x, a0); b0 = fmaf(v.x, w.y, b0);
        a1 = fmaf(v.y, w.x, a1); b1 = fmaf(v.y, w.y, b1);
        a2 = fmaf(v.z, w.x, a2); b2 = fmaf(v.z, w.y, b2);
        a3 = fmaf(v.w, w.x, a3); b3 = fmaf(v.w, w.y, b3);
        w = nx;
        wp += FF;
    }

    if (active && kq > 0) {
        float* myp = red + (kq - 1) * 240 + 2 * slot;
        myp[0]   = a0; myp[1]   = b0;
        myp[60]  = a1; myp[61]  = b1;
        myp[120] = a2; myp[121] = b2;
        myp[180] = a3; myp[181] = b3;
    }
    __syncthreads();
    if (active && kq == 0) {
        float bias0 = nb[col], bias1 = nb[col + 1];
        float sa[4] = {a0 + bias0, a1 + bias0, a2 + bias0, a3 + bias0};
        float sb2[4] = {b0 + bias1, b1 + bias1, b2 + bias1, b3 + bias1};
        const float* p = red + 2 * slot;
#pragma unroll
        for (int q = 0; q < 15; q++) {
#pragma unroll
            for (int r = 0; r < 4; r++) {
                sa[r]  += p[q * 240 + r * 60];
                sb2[r] += p[q * 240 + r * 60 + 1];
            }
        }
#pragma unroll
        for (int r = 0; r < 4; r++)
            *(float2*)&out[(r0 + r) * FF + col] = make_float2(sa[r], sb2[r]);
    }
}

// ---------------- final dense v4: 5-way K-split, window-4 prefetch ----------------
__global__ __launch_bounds__(480) void dense_kernel(
    const float* __restrict__ x,
    const float* __restrict__ dw,
    const float* __restrict__ db,
    float* __restrict__ out)
{
    const int KQ = 48;
    __shared__ __align__(16) float xs[FF * 16];
    __shared__ float red[4 * 16 * 96];

    int r0 = blockIdx.x * 16;
    int c0 = blockIdx.y * 96;
    for (int idx = threadIdx.x; idx < FF * 16; idx += 480) {
        int k = idx >> 4, r = idx & 15;
        xs[idx] = x[(r0 + r) * FF + k];
    }
    __syncthreads();

    int kq = threadIdx.x / 96;
    int c  = threadIdx.x % 96;
    int col = c0 + c;
    int kbeg = kq * KQ;

    float acc[16];
#pragma unroll
    for (int r = 0; r < 16; r++) acc[r] = 0.f;

    const float4* xs4 = (const float4*)xs;
    const float* wp = dw + kbeg * LL + col;
    float w0 = __ldg(wp);
    float w1 = __ldg(wp + LL);
    float w2 = __ldg(wp + 2 * LL);
    float w3 = __ldg(wp + 3 * LL);
    for (int k2 = kbeg; k2 < kbeg + KQ; k2 += 4) {
        float n0 = w0, n1 = w1, n2 = w2, n3 = w3;
        if (k2 + 4 < kbeg + KQ) {
            const float* np = wp + 4 * LL;
            n0 = __ldg(np);
            n1 = __ldg(np + LL);
            n2 = __ldg(np + 2 * LL);
            n3 = __ldg(np + 3 * LL);
        }
#pragma unroll
        for (int kk = 0; kk < 4; kk++) {
            float wf = (kk == 0) ? w0 : (kk == 1) ? w1 : (kk == 2) ? w2 : w3;
            float4 a0 = xs4[(k2 + kk) * 4 + 0];
            float4 a1 = xs4[(k2 + kk) * 4 + 1];
            float4 a2 = xs4[(k2 + kk) * 4 + 2];
            float4 a3 = xs4[(k2 + kk) * 4 + 3];
            acc[ 0] = fmaf(a0.x, wf, acc[ 0]);
            acc[ 1] = fmaf(a0.y, wf, acc[ 1]);
            acc[ 2] = fmaf(a0.z, wf, acc[ 2]);
            acc[ 3] = fmaf(a0.w, wf, acc[ 3]);
            acc[ 4] = fmaf(a1.x, wf, acc[ 4]);
            acc[ 5] = fmaf(a1.y, wf, acc[ 5]);
            acc[ 6] = fmaf(a1.z, wf, acc[ 6]);
            acc[ 7] = fmaf(a1.w, wf, acc[ 7]);
            acc[ 8] = fmaf(a2.x, wf, acc[ 8]);
            acc[ 9] = fmaf(a2.y, wf, acc[ 9]);
            acc[10] = fmaf(a2.z, wf, acc[10]);
            acc[11] = fmaf(a2.w, wf, acc[11]);
            acc[12] = fmaf(a3.x, wf, acc[12]);
            acc[13] = fmaf(a3.y, wf, acc[13]);
            acc[14] = fmaf(a3.z, wf, acc[14]);
            acc[15] = fmaf(a3.w, wf, acc[15]);
        }
        w0 = n0; w1 = n1; w2 = n2; w3 = n3;
        wp += 4 * LL;
    }

    if (kq > 0) {
        float* myp = red + (kq - 1) * 1536 + c;
#pragma unroll
        for (int r = 0; r < 16; r++) myp[r * 96] = acc[r];
    }
    __syncthreads();
    if (kq == 0) {
        float bias = db[col];
        const float* p = red + c;
#pragma unroll
        for (int r = 0; r < 16; r++)
            out[(r0 + r) * LL + col] = acc[r] + bias + p[r * 96] + p[1536 + r * 96]
                                       + p[3072 + r * 96] + p[4608 + r * 96];
    }
}

// ---------------- launch ----------------
extern "C" void kernel_launch(void* const* d_in, const int* in_sizes, int n_in,
                              void* d_out, int out_size)
{
    const float* x      = (const float*)d_in[0];
    const float* a      = (const float*)d_in[1];
    const float* e      = (const float*)d_in[2];
    const float* c1_sw  = (const float*)d_in[3];
    const float* c1_sb  = (const float*)d_in[4];
    const float* c1_aiw = (const float*)d_in[5];
    const float* c1_aib = (const float*)d_in[6];
    const float* c1_ajw = (const float*)d_in[7];
    const float* c1_ajb = (const float*)d_in[8];
    const float* c1_nw  = (const float*)d_in[9];
    const float* c1_nb  = (const float*)d_in[10];
    const float* c1_ew  = (const float*)d_in[11];
    const float* c1_eb  = (const float*)d_in[12];
    const float* c2_sw  = (const float*)d_in[13];
    const float* c2_sb  = (const float*)d_in[14];
    const float* c2_aiw = (const float*)d_in[15];
    const float* c2_aib = (const float*)d_in[16];
    const float* c2_ajw = (const float*)d_in[17];
    const float* c2_ajb = (const float*)d_in[18];
    const float* c2_nw  = (const float*)d_in[19];
    const float* c2_nb  = (const float*)d_in[20];
    const float* c2_ew  = (const float*)d_in[21];
    const float* c2_eb  = (const float*)d_in[22];
    const float* dw     = (const float*)d_in[23];
    const float* db     = (const float*)d_in[24];
    float* out = (float*)d_out;

    float *pU, *pV, *pAi, *pAj, *pE2, *pE2T, *pAT, *pET, *pX2, *pX3;
    cudaGetSymbolAddress((void**)&pU,   g_U);
    cudaGetSymbolAddress((void**)&pV,   g_V);
    cudaGetSymbolAddress((void**)&pAi,  g_aggi);
    cudaGetSymbolAddress((void**)&pAj,  g_aggj);
    cudaGetSymbolAddress((void**)&pE2,  g_e2);
    cudaGetSymbolAddress((void**)&pE2T, g_e2T);
    cudaGetSymbolAddress((void**)&pAT,  g_aT);
    cudaGetSymbolAddress((void**)&pET,  g_eT);
    cudaGetSymbolAddress((void**)&pX2,  g_x2);
    cudaGetSymbolAddress((void**)&pX3,  g_x3);

    // fused prologue: both transposes + layer-1 UV (independent work)
    pre_kernel<<<dim3(200, 3), 512>>>(a, pAT, e, pET, x, c1_sw, pU, pV);

    // ---- layer 1 ----
    pair_both_kernel<<<dim3(NN, 2), 128>>>(pU, pV, e, pET, a, pAT,
        c1_sw + 480 * CC, c1_sw + 481 * CC, c1_sb,
        c1_aiw, c1_aib, c1_ajw, c1_ajb, c1_ew, c1_eb,
        pAi, pAj, pE2, pE2T);
    node_gemm_kernel<<<dim3(100, 4), 512>>>(x, pAi, pAj, c1_nw, c1_nb, pX2);

    // ---- layer 2 (e_out not needed downstream) ----
    uv3_kernel<<<200, 512>>>(pX2, c2_sw, pU, pV);
    pair_both_kernel<<<dim3(NN, 2), 128>>>(pU, pV, pE2, pE2T, a, pAT,
        c2_sw + 480 * CC, c2_sw + 481 * CC, c2_sb,
        c2_aiw, c2_aib, c2_ajw, c2_ajb, nullptr, nullptr,
        pAi, pAj, nullptr, nullptr);
    node_gemm_kernel<<<dim3(100, 4), 512>>>(pX2, pAi, pAj, c2_nw, c2_nb, pX3);

    // ---- final dense ----
    dense_kernel<<<dim3(25, 15), 480>>>(pX3, dw, db, out);
}